// round 2
// baseline (speedup 1.0000x reference)
#include <cuda_runtime.h>

#define A_MAX   500000
#define MAXG    64
#define K1_THREADS 256
#define K1_ITER    4
#define CHUNK   2048
#define NB2_MAX 256
#define LIST_CAP 128

// ------------------------- device scratch (static, no allocs) ---------------
__device__ unsigned long long g_best[MAXG];            // per-gt argmax key
__device__ unsigned int g_codeW[(A_MAX + 3) / 4];      // 1 byte/anchor: (bestg<<2)|cls
__device__ int g_posCnt[NB2_MAX], g_negCnt[NB2_MAX];
__device__ int g_posOff[NB2_MAX], g_negOff[NB2_MAX];
__device__ int g_posTotal, g_negTotal;
__device__ int g_posList[LIST_CAP], g_negList[LIST_CAP];

// ------------------------- K0: zero the per-gt reduction keys ---------------
__global__ void k_init() {
    if (threadIdx.x < MAXG) g_best[threadIdx.x] = 0ull;
}

// ------------------------- K1: IoU + per-anchor max/argmax + per-gt argmax --
__global__ void __launch_bounds__(K1_THREADS) k_iou(
    const float4* __restrict__ anchors, const float4* __restrict__ gts,
    int A, int G)
{
    __shared__ float4 s_gt[MAXG];
    __shared__ float  s_area[MAXG];
    __shared__ unsigned long long s_best[MAXG];

    int tid = threadIdx.x;
    if (tid < G) {
        float4 g = gts[tid];
        s_gt[tid] = g;
        // __fmul_rn: forbid FMA contraction so rounding matches the reference
        s_area[tid] = __fmul_rn(g.z - g.x, g.w - g.y);
    }
    if (tid < MAXG) s_best[tid] = 0ull;
    __syncthreads();

    unsigned char* g_code = (unsigned char*)g_codeW;
    int lane = tid & 31;

    for (int k = 0; k < K1_ITER; k++) {
        int i = (blockIdx.x * K1_ITER + k) * K1_THREADS + tid;
        bool valid = (i < A);
        float4 a = anchors[valid ? i : 0];
        float sa = __fmul_rn(a.z - a.x, a.w - a.y);
        float best = -1.0f; int bestg = 0;
        unsigned idxkey = valid ? ~(unsigned)i : 0u;

        #pragma unroll 8
        for (int g = 0; g < MAXG; g++) {
            float4 gt = s_gt[g];
            float w = fminf(a.z, gt.z) - fmaxf(a.x, gt.x);
            float h = fminf(a.w, gt.w) - fmaxf(a.y, gt.y);
            w = fmaxf(w, 0.0f);
            h = fmaxf(h, 0.0f);
            float inter = __fmul_rn(w, h);
            float den = (sa + s_area[g]) - inter;   // adds only, no contraction risk
            float iou = inter / den;                // IEEE div.rn, matches reference
            if (iou > best) { best = iou; bestg = g; }  // first-occurrence argmax

            // per-gt reduction: max iou, tie-break = smallest anchor index
            unsigned b = valid ? __float_as_uint(iou) : 0u;  // iou >= 0 -> bit order ok
            unsigned mx = __reduce_max_sync(0xffffffffu, b);
            unsigned msk = __ballot_sync(0xffffffffu, b == mx);
            if (lane == __ffs(msk) - 1) {
                atomicMax(&s_best[g], ((unsigned long long)mx << 32) | idxkey);
            }
        }

        if (valid) {
            int cls = (best > 0.5f) ? 2 : ((best < 0.3f) ? 0 : 1);
            g_code[i] = (unsigned char)((bestg << 2) | cls);
        }
    }

    __syncthreads();
    if (tid < G) atomicMax(&g_best[tid], s_best[tid]);
}

// --------- K1b: force-pos the gt_argmax anchors (cls -> 3, keep bestg) ------
__global__ void k_mark(int A, int G) {
    int g = threadIdx.x;
    if (g < G) {
        unsigned long long key = g_best[g];
        unsigned idx = ~(unsigned)(key & 0xffffffffull);
        if (idx < (unsigned)A) {
            atomicOr(&g_codeW[idx >> 2], 3u << ((idx & 3) * 8));
        }
    }
}

// ------------------------- K2a: per-block pos/neg counts --------------------
__global__ void __launch_bounds__(256) k_count(int A) {
    const unsigned char* g_code = (const unsigned char*)g_codeW;
    int base = blockIdx.x * CHUNK + threadIdx.x * 8;
    int p = 0, n = 0;
    #pragma unroll
    for (int j = 0; j < 8; j++) {
        int i = base + j;
        if (i < A) {
            int c = g_code[i] & 3;
            p += (c >= 2);
            n += (c == 0);
        }
    }
    __shared__ int sp[256], sn[256];
    sp[threadIdx.x] = p; sn[threadIdx.x] = n;
    __syncthreads();
    for (int s = 128; s > 0; s >>= 1) {
        if (threadIdx.x < s) {
            sp[threadIdx.x] += sp[threadIdx.x + s];
            sn[threadIdx.x] += sn[threadIdx.x + s];
        }
        __syncthreads();
    }
    if (threadIdx.x == 0) {
        g_posCnt[blockIdx.x] = sp[0];
        g_negCnt[blockIdx.x] = sn[0];
    }
}

// ------------------------- K2b: scan of block counts (1 block) --------------
__global__ void __launch_bounds__(256) k_scan(int nb) {
    __shared__ int sp[256], sn[256];
    int t = threadIdx.x;
    int p = (t < nb && t < NB2_MAX) ? g_posCnt[t] : 0;
    int n = (t < nb && t < NB2_MAX) ? g_negCnt[t] : 0;
    sp[t] = p; sn[t] = n;
    __syncthreads();
    for (int off = 1; off < 256; off <<= 1) {
        int vp = (t >= off) ? sp[t - off] : 0;
        int vn = (t >= off) ? sn[t - off] : 0;
        __syncthreads();
        sp[t] += vp; sn[t] += vn;
        __syncthreads();
    }
    if (t < nb && t < NB2_MAX) {
        g_posOff[t] = sp[t] - p;
        g_negOff[t] = sn[t] - n;
    }
    if (t == 255) {
        g_posTotal = sp[255];
        g_negTotal = sn[255];
    }
}

// ------------- K2c: scatter first-128 ordered pos / neg indices -------------
__global__ void __launch_bounds__(256) k_scatter(int A) {
    const unsigned char* g_code = (const unsigned char*)g_codeW;
    __shared__ int sp[256], sn[256];
    int t = threadIdx.x;
    int base = blockIdx.x * CHUNK + t * 8;
    int pc = 0, nc = 0;
    unsigned char codes[8];
    #pragma unroll
    for (int j = 0; j < 8; j++) {
        int i = base + j;
        unsigned char c = (i < A) ? g_code[i] : (unsigned char)1;
        codes[j] = c;
        int cl = c & 3;
        pc += (cl >= 2);
        nc += (cl == 0);
    }
    sp[t] = pc; sn[t] = nc;
    __syncthreads();
    for (int off = 1; off < 256; off <<= 1) {
        int vp = (t >= off) ? sp[t - off] : 0;
        int vn = (t >= off) ? sn[t - off] : 0;
        __syncthreads();
        sp[t] += vp; sn[t] += vn;
        __syncthreads();
    }
    int pr = g_posOff[blockIdx.x] + sp[t] - pc;
    int nr = g_negOff[blockIdx.x] + sn[t] - nc;
    #pragma unroll
    for (int j = 0; j < 8; j++) {
        int i = base + j;
        if (i < A) {
            int cl = codes[j] & 3;
            if (cl >= 2)       { if (pr < LIST_CAP) g_posList[pr] = i; pr++; }
            else if (cl == 0)  { if (nr < LIST_CAP) g_negList[nr] = i; nr++; }
        }
    }
}

// ------------------------- K3: losses (1 block) -----------------------------
__global__ void __launch_bounds__(256) k_loss(
    const float* __restrict__ score, const float4* __restrict__ regp,
    const float4* __restrict__ anchors, const float4* __restrict__ gts,
    float* __restrict__ out, int out_size)
{
    const unsigned char* g_code = (const unsigned char*)g_codeW;
    int t = threadIdx.x;
    int posTotal = g_posTotal, negTotal = g_negTotal;
    bool bug = (posTotal >= LIST_CAP);
    int P = bug ? LIST_CAP : posTotal;
    int nbound = bug ? LIST_CAP : P;   // non-bug: int(P/0.5*0.5) == P
    int Nn = min(nbound, negTotal);

    float cls = 0.f, reg = 0.f, ncls = 0.f;

    for (int i = t; i < P; i += blockDim.x) {
        int idx = g_posList[i];
        float4 a = anchors[idx];
        float lse, x0;
        if (bug) {
            float m = fmaxf(fmaxf(a.x, a.y), fmaxf(a.z, a.w));
            float s = expf(a.x - m) + expf(a.y - m) + expf(a.z - m) + expf(a.w - m);
            lse = m + logf(s); x0 = a.x;
        } else {
            float s0 = score[2 * idx], s1 = score[2 * idx + 1];
            float m = fmaxf(s0, s1);
            lse = m + logf(expf(s0 - m) + expf(s1 - m)); x0 = s0;
        }
        cls += lse - x0;

        int gidx = g_code[idx] >> 2;
        float4 g = gts[gidx];
        float aw = a.z - a.x, ah = a.w - a.y;
        float acx = a.x + aw * 0.5f, acy = a.y + ah * 0.5f;
        float gw = g.z - g.x, gh = g.w - g.y;
        float gcx = g.x + gw * 0.5f, gcy = g.y + gh * 0.5f;
        float tx = (gcx - acx) / aw;
        float ty = (gcy - acy) / ah;
        float tw = logf(gw / aw);
        float th = logf(gh / ah);
        float4 r = regp[idx];
        float d, ad;
        d = r.x - tx; ad = fabsf(d); reg += (ad < 1.f) ? 0.5f * d * d : ad - 0.5f;
        d = r.y - ty; ad = fabsf(d); reg += (ad < 1.f) ? 0.5f * d * d : ad - 0.5f;
        d = r.z - tw; ad = fabsf(d); reg += (ad < 1.f) ? 0.5f * d * d : ad - 0.5f;
        d = r.w - th; ad = fabsf(d); reg += (ad < 1.f) ? 0.5f * d * d : ad - 0.5f;
    }

    for (int i = t; i < Nn; i += blockDim.x) {
        int idx = g_negList[i];
        float s0 = score[2 * idx], s1 = score[2 * idx + 1];
        float m = fmaxf(s0, s1);
        float lse = m + logf(expf(s0 - m) + expf(s1 - m));
        ncls += lse - s1;
    }

    __shared__ float sc[256], sr[256], sn2[256];
    sc[t] = cls; sr[t] = reg; sn2[t] = ncls;
    __syncthreads();
    for (int s = 128; s > 0; s >>= 1) {
        if (t < s) { sc[t] += sc[t + s]; sr[t] += sr[t + s]; sn2[t] += sn2[t + s]; }
        __syncthreads();
    }
    if (t == 0) {
        float pc = (P  > 0) ? sc[0]  / (float)P  : 0.f;
        float rg = (P  > 0) ? sr[0]  / (float)P  : 0.f;
        float nc = (Nn > 0) ? sn2[0] / (float)Nn : 0.f;
        float v = pc + rg + nc;
        for (int o = 0; o < out_size; o++) out[o] = v;
    }
}

// ------------------------- host launcher ------------------------------------
extern "C" void kernel_launch(void* const* d_in, const int* in_sizes, int n_in,
                              void* d_out, int out_size) {
    const float*  score   = (const float*)d_in[0];      // (A,2)
    const float4* regp    = (const float4*)d_in[1];     // (A,4)
    const float4* anchors = (const float4*)d_in[2];     // (A,4)
    const float4* gts     = (const float4*)d_in[3];     // (G,4)
    int A = in_sizes[0] / 2;
    int G = in_sizes[3] / 4;

    k_init<<<1, 64>>>();
    int grid1 = (A + K1_THREADS * K1_ITER - 1) / (K1_THREADS * K1_ITER);
    k_iou<<<grid1, K1_THREADS>>>(anchors, gts, A, G);
    k_mark<<<1, 64>>>(A, G);
    int nb2 = (A + CHUNK - 1) / CHUNK;
    k_count<<<nb2, 256>>>(A);
    k_scan<<<1, 256>>>(nb2);
    k_scatter<<<nb2, 256>>>(A);
    k_loss<<<1, 256>>>(score, regp, anchors, gts, (float*)d_out, out_size);
}

// round 4
// speedup vs baseline: 1.9082x; 1.9082x over previous
#include <cuda_runtime.h>

#define A_CAP   500000
#define MAXG    64
#define K1_THREADS 256
#define K1_ITER 4
#define CHUNK   2048
#define NB_MAX  256
#define LIST_CAP 128

// ---------------- device scratch (static, zero-init; k_loss re-zeros g_best) -
__device__ unsigned long long g_best[MAXG];          // (iou_bits<<32)|~anchor_idx
__device__ unsigned int g_codeW[(A_CAP + 3) / 4];    // byte/anchor: (bestg<<2)|cls
__device__ int g_posCnt[NB_MAX], g_negCnt[NB_MAX];
__device__ int g_posList[LIST_CAP], g_negList[LIST_CAP];

// ---------------- K1: IoU + per-anchor max/argmax + per-gt argmax ------------
__global__ void __launch_bounds__(K1_THREADS) k_iou(
    const float4* __restrict__ anchors, const float4* __restrict__ gts,
    int A, int G)
{
    __shared__ float4 s_gt[MAXG];
    __shared__ float  s_area[MAXG];
    __shared__ unsigned long long s_best[MAXG];

    int tid = threadIdx.x;
    if (tid < G) {
        float4 g = gts[tid];
        s_gt[tid] = g;
        s_area[tid] = __fmul_rn(g.z - g.x, g.w - g.y);  // no FMA contraction
    }
    if (tid < MAXG) s_best[tid] = 0ull;
    __syncthreads();

    unsigned char* g_code = (unsigned char*)g_codeW;

    for (int k = 0; k < K1_ITER; k++) {
        int i = (blockIdx.x * K1_ITER + k) * K1_THREADS + tid;
        bool valid = (i < A);
        float4 a;
        if (valid) a = anchors[i];
        else       a = make_float4(-3e8f, -3e8f, -3e8f, -3e8f);  // no overlap ever
        float sa = __fmul_rn(a.z - a.x, a.w - a.y);
        float best = -1.0f; int bestg = 0;
        unsigned idxkey = ~(unsigned)i;

        #pragma unroll 8
        for (int g = 0; g < MAXG; g++) {
            if (g >= G) break;
            float4 gt = s_gt[g];
            float w = fminf(a.z, gt.z) - fmaxf(a.x, gt.x);
            float h = fminf(a.w, gt.w) - fmaxf(a.y, gt.y);
            float inter = __fmul_rn(fmaxf(w, 0.0f), fmaxf(h, 0.0f));
            if (inter > 0.0f) {                       // skip non-overlapping pairs
                float den = (sa + s_area[g]) - inter; // adds only
                float iou = inter / den;              // IEEE div.rn
                if (iou > best) { best = iou; bestg = g; }  // first-occurrence
                unsigned hi = ((const unsigned*)&s_best[g])[1];  // broadcast LDS
                // >= : on exact IoU ties the smaller anchor index must still
                // get a chance to win via the |~idx key (argmax first-occurrence)
                if (__float_as_uint(iou) >= hi) {     // rare
                    atomicMax(&s_best[g],
                        ((unsigned long long)__float_as_uint(iou) << 32) | idxkey);
                }
            }
        }

        if (valid) {
            // best==-1 (all zero IoU) -> cls 0 (neg), bestg 0: matches reference
            int cls = (best > 0.5f) ? 2 : ((best < 0.3f) ? 0 : 1);
            g_code[i] = (unsigned char)((bestg << 2) | cls);
        }
    }

    __syncthreads();
    if (tid < G) {
        unsigned long long v = s_best[tid];
        if (v) atomicMax(&g_best[tid], v);
    }
}

// ------------- forced-anchor bitmap helper (gt_argmax anchors, per block) ----
__device__ __forceinline__ void build_forced_mask(unsigned* s_mask, int base,
                                                  int A, int G) {
    int t = threadIdx.x;
    if (t < CHUNK / 32) s_mask[t] = 0u;
    __syncthreads();
    if (t < G) {
        unsigned long long key = g_best[t];
        // key==0 (no overlap for this gt) -> reference argmax = anchor 0
        unsigned idx = key ? ~(unsigned)(key & 0xffffffffull) : 0u;
        if (idx < (unsigned)A && (int)idx >= base && (int)idx < base + CHUNK) {
            unsigned off = idx - base;
            atomicOr(&s_mask[off >> 5], 1u << (off & 31));
        }
    }
    __syncthreads();
}

// ---------------- K2: per-block pos/neg counts (with forced override) --------
__global__ void __launch_bounds__(256) k_count(int A, int G) {
    __shared__ unsigned s_mask[CHUNK / 32];
    int t = threadIdx.x, bid = blockIdx.x;
    int base = bid * CHUNK;
    build_forced_mask(s_mask, base, A, G);

    int p = 0, n = 0;
    #pragma unroll
    for (int wj = 0; wj < 2; wj++) {
        int wi = (base >> 2) + t * 2 + wj;      // word index into g_codeW
        int i0 = wi * 4;
        if (i0 < A) {
            unsigned wv = g_codeW[wi];
            unsigned off = (unsigned)(i0 - base);
            unsigned fm = (s_mask[off >> 5] >> (off & 31)) & 0xFu;
            #pragma unroll
            for (int b = 0; b < 4; b++) {
                if (i0 + b < A) {
                    int cls = (wv >> (8 * b)) & 3;
                    int forced = (fm >> b) & 1;
                    p += ((cls >= 2) | forced);
                    n += ((cls == 0) & (forced ^ 1));
                }
            }
        }
    }
    __shared__ int sp[256], sn[256];
    sp[t] = p; sn[t] = n;
    __syncthreads();
    for (int s = 128; s > 0; s >>= 1) {
        if (t < s) { sp[t] += sp[t + s]; sn[t] += sn[t + s]; }
        __syncthreads();
    }
    if (t == 0) { g_posCnt[bid] = sp[0]; g_negCnt[bid] = sn[0]; }
}

// ---------------- K3: ordered scatter of first-128 pos / neg ----------------
__global__ void __launch_bounds__(256) k_scatter(int A, int G, int nb) {
    __shared__ unsigned s_mask[CHUNK / 32];
    __shared__ int sp[256], sn[256];
    __shared__ int s_pb, s_nb;
    int t = threadIdx.x, bid = blockIdx.x;
    int base = bid * CHUNK;

    // block prefix = sum of counts of earlier blocks
    int pv = (t < bid) ? g_posCnt[t] : 0;
    int nv = (t < bid) ? g_negCnt[t] : 0;
    sp[t] = pv; sn[t] = nv;
    __syncthreads();
    for (int s = 128; s > 0; s >>= 1) {
        if (t < s) { sp[t] += sp[t + s]; sn[t] += sn[t + s]; }
        __syncthreads();
    }
    if (t == 0) { s_pb = sp[0]; s_nb = sn[0]; }
    __syncthreads();
    int posBase = s_pb, negBase = s_nb;
    if (posBase >= LIST_CAP && negBase >= LIST_CAP) return;  // nothing to write
    __syncthreads();

    build_forced_mask(s_mask, base, A, G);

    // local classification (8 anchors/thread) + thread counts
    unsigned char cl[8];
    int pc = 0, nc = 0;
    #pragma unroll
    for (int wj = 0; wj < 2; wj++) {
        int wi = (base >> 2) + t * 2 + wj;
        int i0 = wi * 4;
        unsigned wv = (i0 < A) ? g_codeW[wi] : 0x01010101u;  // pad: ignore-class
        unsigned off = (unsigned)(i0 - base);
        unsigned fm = (i0 < A) ? ((s_mask[off >> 5] >> (off & 31)) & 0xFu) : 0u;
        #pragma unroll
        for (int b = 0; b < 4; b++) {
            int cls = (wv >> (8 * b)) & 3;
            if (i0 + b >= A) cls = 1;
            if ((fm >> b) & 1) cls = 3;
            cl[wj * 4 + b] = (unsigned char)cls;
            pc += (cls >= 2);
            nc += (cls == 0);
        }
    }
    __syncthreads();   // reuse sp/sn
    sp[t] = pc; sn[t] = nc;
    __syncthreads();
    for (int off = 1; off < 256; off <<= 1) {
        int vp = (t >= off) ? sp[t - off] : 0;
        int vn = (t >= off) ? sn[t - off] : 0;
        __syncthreads();
        sp[t] += vp; sn[t] += vn;
        __syncthreads();
    }
    int pr = posBase + sp[t] - pc;
    int nr = negBase + sn[t] - nc;
    #pragma unroll
    for (int j = 0; j < 8; j++) {
        int i = base + t * 8 + j;
        int cls = cl[j];
        if (cls >= 2)      { if (pr < LIST_CAP) g_posList[pr] = i; pr++; }
        else if (cls == 0) { if (nr < LIST_CAP) g_negList[nr] = i; nr++; }
    }
}

// ---------------- K4: losses (1 block) + re-zero g_best ---------------------
__global__ void __launch_bounds__(256) k_loss(
    const float* __restrict__ score, const float4* __restrict__ regp,
    const float4* __restrict__ anchors, const float4* __restrict__ gts,
    float* __restrict__ out, int out_size, int nb)
{
    const unsigned char* g_code = (const unsigned char*)g_codeW;
    __shared__ int sp[256], sn[256];
    __shared__ int s_pt, s_nt;
    int t = threadIdx.x;

    // totals
    int pv = (t < nb) ? g_posCnt[t] : 0;
    int nv = (t < nb) ? g_negCnt[t] : 0;
    sp[t] = pv; sn[t] = nv;
    __syncthreads();
    for (int s = 128; s > 0; s >>= 1) {
        if (t < s) { sp[t] += sp[t + s]; sn[t] += sn[t + s]; }
        __syncthreads();
    }
    if (t == 0) { s_pt = sp[0]; s_nt = sn[0]; }
    __syncthreads();
    int posTotal = s_pt, negTotal = s_nt;

    bool bug = (posTotal >= LIST_CAP);
    int P = bug ? LIST_CAP : posTotal;
    int Nn = min(bug ? LIST_CAP : P, negTotal);

    float cls = 0.f, reg = 0.f, ncls = 0.f;

    for (int i = t; i < P; i += blockDim.x) {
        int idx = g_posList[i];
        float4 a = anchors[idx];
        float lse, x0;
        if (bug) {
            float m = fmaxf(fmaxf(a.x, a.y), fmaxf(a.z, a.w));
            float s = expf(a.x - m) + expf(a.y - m) + expf(a.z - m) + expf(a.w - m);
            lse = m + logf(s); x0 = a.x;
        } else {
            float s0 = score[2 * idx], s1 = score[2 * idx + 1];
            float m = fmaxf(s0, s1);
            lse = m + logf(expf(s0 - m) + expf(s1 - m)); x0 = s0;
        }
        cls += lse - x0;

        int gidx = g_code[idx] >> 2;
        float4 g = gts[gidx];
        float aw = a.z - a.x, ah = a.w - a.y;
        float acx = a.x + aw * 0.5f, acy = a.y + ah * 0.5f;
        float gw = g.z - g.x, gh = g.w - g.y;
        float gcx = g.x + gw * 0.5f, gcy = g.y + gh * 0.5f;
        float tx = (gcx - acx) / aw;
        float ty = (gcy - acy) / ah;
        float tw = logf(gw / aw);
        float th = logf(gh / ah);
        float4 r = regp[idx];
        float d, ad;
        d = r.x - tx; ad = fabsf(d); reg += (ad < 1.f) ? 0.5f * d * d : ad - 0.5f;
        d = r.y - ty; ad = fabsf(d); reg += (ad < 1.f) ? 0.5f * d * d : ad - 0.5f;
        d = r.z - tw; ad = fabsf(d); reg += (ad < 1.f) ? 0.5f * d * d : ad - 0.5f;
        d = r.w - th; ad = fabsf(d); reg += (ad < 1.f) ? 0.5f * d * d : ad - 0.5f;
    }

    for (int i = t; i < Nn; i += blockDim.x) {
        int idx = g_negList[i];
        float s0 = score[2 * idx], s1 = score[2 * idx + 1];
        float m = fmaxf(s0, s1);
        float lse = m + logf(expf(s0 - m) + expf(s1 - m));
        ncls += lse - s1;
    }

    __shared__ float fc[256], fr[256], fn[256];
    fc[t] = cls; fr[t] = reg; fn[t] = ncls;
    __syncthreads();
    for (int s = 128; s > 0; s >>= 1) {
        if (t < s) { fc[t] += fc[t + s]; fr[t] += fr[t + s]; fn[t] += fn[t + s]; }
        __syncthreads();
    }
    if (t == 0) {
        float pc = (P  > 0) ? fc[0] / (float)P  : 0.f;
        float rg = (P  > 0) ? fr[0] / (float)P  : 0.f;
        float nc = (Nn > 0) ? fn[0] / (float)Nn : 0.f;
        float v = pc + rg + nc;
        for (int o = 0; o < out_size; o++) out[o] = v;
    }
    // re-zero g_best so the next graph replay starts clean
    if (t < MAXG) g_best[t] = 0ull;
}

// ---------------- host launcher ---------------------------------------------
extern "C" void kernel_launch(void* const* d_in, const int* in_sizes, int n_in,
                              void* d_out, int out_size) {
    const float*  score   = (const float*)d_in[0];      // (A,2)
    const float4* regp    = (const float4*)d_in[1];     // (A,4)
    const float4* anchors = (const float4*)d_in[2];     // (A,4)
    const float4* gts     = (const float4*)d_in[3];     // (G,4)
    int A = in_sizes[0] / 2;
    int G = in_sizes[3] / 4;
    if (G > MAXG) G = MAXG;

    int grid1 = (A + K1_THREADS * K1_ITER - 1) / (K1_THREADS * K1_ITER);
    int nb = (A + CHUNK - 1) / CHUNK;

    k_iou<<<grid1, K1_THREADS>>>(anchors, gts, A, G);
    k_count<<<nb, 256>>>(A, G);
    k_scatter<<<nb, 256>>>(A, G, nb);
    k_loss<<<1, 256>>>(score, regp, anchors, gts, (float*)d_out, out_size, nb);
}

// round 5
// speedup vs baseline: 1.9951x; 1.0455x over previous
#include <cuda_runtime.h>

#define A_CAP   500000
#define MAXG    64
#define K1_THREADS 256
#define K1_ITER 4
#define CHUNK   2048
#define NB_MAX  256
#define LIST_CAP 128

// ------------- device scratch (static zero-init; k_post resets at end) ------
__device__ unsigned long long g_best[MAXG];          // (iou_bits<<32)|~anchor_idx
__device__ unsigned int g_codeW[(A_CAP + 3) / 4];    // byte/anchor: (bestg<<2)|cls
__device__ int g_posCnt[NB_MAX], g_negCnt[NB_MAX];
__device__ int g_posList[LIST_CAP], g_negList[LIST_CAP];
__device__ int g_done1, g_done2;

// ---------------- K1: IoU + per-anchor argmax + per-gt argmax ----------------
__global__ void __launch_bounds__(K1_THREADS) k_iou(
    const float4* __restrict__ anchors, const float4* __restrict__ gts,
    int A, int G)
{
    __shared__ float4 s_gt[MAXG];
    __shared__ float  s_area[MAXG];
    __shared__ unsigned long long s_best[MAXG];

    int tid = threadIdx.x;
    if (tid < G) {
        float4 g = gts[tid];
        s_gt[tid] = g;
        s_area[tid] = __fmul_rn(g.z - g.x, g.w - g.y);  // no FMA contraction
    }
    if (tid < MAXG) s_best[tid] = 0ull;
    __syncthreads();

    unsigned char* g_code = (unsigned char*)g_codeW;

    for (int k = 0; k < K1_ITER; k++) {
        int i = (blockIdx.x * K1_ITER + k) * K1_THREADS + tid;
        bool valid = (i < A);
        float4 a;
        if (valid) a = anchors[i];
        else       a = make_float4(-3e8f, -3e8f, -3e8f, -3e8f);  // never overlaps
        float sa = __fmul_rn(a.z - a.x, a.w - a.y);
        // cross-mult running argmax: best iou = bi/bd (bi=0,bd=1 -> iou 0)
        float bi = 0.0f, bd = 1.0f;
        int bestg = 0;
        unsigned idxkey = ~(unsigned)i;

        #pragma unroll 8
        for (int g = 0; g < MAXG; g++) {
            if (g >= G) break;
            float4 gt = s_gt[g];
            float w = fminf(a.z, gt.z) - fmaxf(a.x, gt.x);
            float h = fminf(a.w, gt.w) - fmaxf(a.y, gt.y);
            float inter = __fmul_rn(fmaxf(w, 0.0f), fmaxf(h, 0.0f));
            if (inter > 0.0f) {
                float den = (sa + s_area[g]) - inter;   // adds only
                // iou_g > best  <=>  inter*bd > bi*den ; exact tie keeps earlier
                if (__fmul_rn(inter, bd) > __fmul_rn(bi, den)) {
                    bi = inter; bd = den; bestg = g;
                }
                // per-gt guard: superset of round(inter/den) >= current best bits
                unsigned hibits = ((const unsigned*)&s_best[g])[1];
                float hv = __uint_as_float(hibits);
                if (inter > __fmul_rn(__fmul_rn(hv, 0.9999995f), den)) {
                    float iou = inter / den;            // IEEE div.rn (rare)
                    unsigned ib = __float_as_uint(iou);
                    if (ib >= hibits) {                 // >=: tie -> smaller idx can win
                        atomicMax(&s_best[g],
                            ((unsigned long long)ib << 32) | idxkey);
                    }
                }
            }
        }

        if (valid) {
            float bestIou = bi / bd;   // single IEEE div per anchor, matches ref bits
            int cls = (bestIou > 0.5f) ? 2 : ((bestIou < 0.3f) ? 0 : 1);
            g_code[i] = (unsigned char)((bestg << 2) | cls);
        }
    }

    __syncthreads();
    if (tid < G) {
        unsigned long long v = s_best[tid];
        if (v) atomicMax(&g_best[tid], v);
    }
}

// ------- K2 (fused): classify+count -> grid sync -> scatter -> loss ---------
__global__ void __launch_bounds__(256) k_post(
    const float* __restrict__ score, const float4* __restrict__ regp,
    const float4* __restrict__ anchors, const float4* __restrict__ gts,
    float* __restrict__ out, int out_size, int A, int G, int nb)
{
    __shared__ unsigned s_mask[CHUNK / 32];
    __shared__ int sp[256], sn[256];
    __shared__ int s_b0, s_b1, s_flag;
    int t = threadIdx.x, bid = blockIdx.x;
    int base = bid * CHUNK;

    // ---- phase 0: forced gt-argmax bitmap for this block's chunk ----
    if (t < CHUNK / 32) s_mask[t] = 0u;
    __syncthreads();
    if (t < G) {
        unsigned long long key = g_best[t];
        // key==0 (gt overlaps nothing) -> reference argmax = anchor 0
        unsigned idx = key ? ~(unsigned)(key & 0xffffffffull) : 0u;
        if (idx < (unsigned)A && (int)idx >= base && (int)idx < base + CHUNK) {
            unsigned off = idx - base;
            atomicOr(&s_mask[off >> 5], 1u << (off & 31));
        }
    }
    __syncthreads();

    // ---- phase 1: classify 8 anchors/thread (kept in regs), count ----
    unsigned char cl[8];
    int pc = 0, nc = 0;
    #pragma unroll
    for (int wj = 0; wj < 2; wj++) {
        int wi = (base >> 2) + t * 2 + wj;
        int i0 = wi * 4;
        unsigned wv = (i0 < A) ? g_codeW[wi] : 0x01010101u;  // pad: ignore class
        unsigned off = (unsigned)(i0 - base);
        unsigned fm = (i0 < A) ? ((s_mask[off >> 5] >> (off & 31)) & 0xFu) : 0u;
        #pragma unroll
        for (int b = 0; b < 4; b++) {
            int cls = (wv >> (8 * b)) & 3;
            if (i0 + b >= A) cls = 1;
            if ((fm >> b) & 1) cls = 3;
            cl[wj * 4 + b] = (unsigned char)cls;
            pc += (cls >= 2);
            nc += (cls == 0);
        }
    }
    sp[t] = pc; sn[t] = nc;
    __syncthreads();
    for (int s = 128; s > 0; s >>= 1) {
        if (t < s) { sp[t] += sp[t + s]; sn[t] += sn[t + s]; }
        __syncthreads();
    }
    if (t == 0) {
        g_posCnt[bid] = sp[0];
        g_negCnt[bid] = sn[0];
        __threadfence();
        atomicAdd(&g_done1, 1);
    }

    // ---- grid sync 1: wait for all counts ----
    if (t == 0) {
        while (atomicAdd(&g_done1, 0) < nb) __nanosleep(64);
    }
    __syncthreads();
    __threadfence();

    // ---- phase 2: block prefix over earlier blocks, then ordered scatter ----
    sp[t] = (t < bid) ? g_posCnt[t] : 0;
    sn[t] = (t < bid) ? g_negCnt[t] : 0;
    __syncthreads();
    for (int s = 128; s > 0; s >>= 1) {
        if (t < s) { sp[t] += sp[t + s]; sn[t] += sn[t + s]; }
        __syncthreads();
    }
    if (t == 0) { s_b0 = sp[0]; s_b1 = sn[0]; }
    __syncthreads();
    int posBase = s_b0, negBase = s_b1;

    if (posBase < LIST_CAP || negBase < LIST_CAP) {
        __syncthreads();
        sp[t] = pc; sn[t] = nc;       // intra-block inclusive scan
        __syncthreads();
        for (int off = 1; off < 256; off <<= 1) {
            int vp = (t >= off) ? sp[t - off] : 0;
            int vn = (t >= off) ? sn[t - off] : 0;
            __syncthreads();
            sp[t] += vp; sn[t] += vn;
            __syncthreads();
        }
        int pr = posBase + sp[t] - pc;
        int nr = negBase + sn[t] - nc;
        #pragma unroll
        for (int j = 0; j < 8; j++) {
            int i = base + t * 8 + j;
            int cls = cl[j];
            if (cls >= 2)      { if (pr < LIST_CAP) g_posList[pr] = i; pr++; }
            else if (cls == 0) { if (nr < LIST_CAP) g_negList[nr] = i; nr++; }
        }
    }
    __syncthreads();

    // ---- grid sync 2: last block to finish scatter runs the loss ----
    if (t == 0) {
        __threadfence();
        int old = atomicAdd(&g_done2, 1);
        s_flag = (old == nb - 1);
    }
    __syncthreads();
    if (!s_flag) return;
    __threadfence();

    // ---- phase 3: totals ----
    sp[t] = (t < nb) ? g_posCnt[t] : 0;
    sn[t] = (t < nb) ? g_negCnt[t] : 0;
    __syncthreads();
    for (int s = 128; s > 0; s >>= 1) {
        if (t < s) { sp[t] += sp[t + s]; sn[t] += sn[t + s]; }
        __syncthreads();
    }
    if (t == 0) { s_b0 = sp[0]; s_b1 = sn[0]; }
    __syncthreads();
    int posTotal = s_b0, negTotal = s_b1;

    bool bug = (posTotal >= LIST_CAP);
    int P = bug ? LIST_CAP : posTotal;                 // P <= 128
    int Nn = min(bug ? LIST_CAP : P, negTotal);        // Nn <= 128

    const unsigned char* g_code = (const unsigned char*)g_codeW;
    float cls = 0.f, reg = 0.f, ncls = 0.f;

    if (t < LIST_CAP) {
        // threads 0..127: one positive item each
        if (t < P) {
            int idx = g_posList[t];
            float4 a = anchors[idx];
            float lse, x0;
            if (bug) {
                float m = fmaxf(fmaxf(a.x, a.y), fmaxf(a.z, a.w));
                float s = expf(a.x - m) + expf(a.y - m) + expf(a.z - m) + expf(a.w - m);
                lse = m + logf(s); x0 = a.x;
            } else {
                float s0 = score[2 * idx], s1 = score[2 * idx + 1];
                float m = fmaxf(s0, s1);
                lse = m + logf(expf(s0 - m) + expf(s1 - m)); x0 = s0;
            }
            cls = lse - x0;

            int gidx = g_code[idx] >> 2;
            float4 g = gts[gidx];
            float aw = a.z - a.x, ah = a.w - a.y;
            float acx = a.x + aw * 0.5f, acy = a.y + ah * 0.5f;
            float gw = g.z - g.x, gh = g.w - g.y;
            float gcx = g.x + gw * 0.5f, gcy = g.y + gh * 0.5f;
            float tx = (gcx - acx) / aw;
            float ty = (gcy - acy) / ah;
            float tw = logf(gw / aw);
            float th = logf(gh / ah);
            float4 r = regp[idx];
            float d, ad;
            d = r.x - tx; ad = fabsf(d); reg += (ad < 1.f) ? 0.5f * d * d : ad - 0.5f;
            d = r.y - ty; ad = fabsf(d); reg += (ad < 1.f) ? 0.5f * d * d : ad - 0.5f;
            d = r.z - tw; ad = fabsf(d); reg += (ad < 1.f) ? 0.5f * d * d : ad - 0.5f;
            d = r.w - th; ad = fabsf(d); reg += (ad < 1.f) ? 0.5f * d * d : ad - 0.5f;
        }
    } else {
        // threads 128..255: one negative item each
        int j = t - LIST_CAP;
        if (j < Nn) {
            int idx = g_negList[j];
            float s0 = score[2 * idx], s1 = score[2 * idx + 1];
            float m = fmaxf(s0, s1);
            float lse = m + logf(expf(s0 - m) + expf(s1 - m));
            ncls = lse - s1;
        }
    }

    __shared__ float fc[256], fr[256], fn[256];
    fc[t] = cls; fr[t] = reg; fn[t] = ncls;
    __syncthreads();
    for (int s = 128; s > 0; s >>= 1) {
        if (t < s) { fc[t] += fc[t + s]; fr[t] += fr[t + s]; fn[t] += fn[t + s]; }
        __syncthreads();
    }
    if (t == 0) {
        float pcl = (P  > 0) ? fc[0] / (float)P  : 0.f;
        float rg  = (P  > 0) ? fr[0] / (float)P  : 0.f;
        float ncl = (Nn > 0) ? fn[0] / (float)Nn : 0.f;
        float v = pcl + rg + ncl;
        for (int o = 0; o < out_size; o++) out[o] = v;
        g_done1 = 0;
        g_done2 = 0;
    }
    if (t < MAXG) g_best[t] = 0ull;   // clean state for next graph replay
}

// ---------------- host launcher ---------------------------------------------
extern "C" void kernel_launch(void* const* d_in, const int* in_sizes, int n_in,
                              void* d_out, int out_size) {
    const float*  score   = (const float*)d_in[0];      // (A,2)
    const float4* regp    = (const float4*)d_in[1];     // (A,4)
    const float4* anchors = (const float4*)d_in[2];     // (A,4)
    const float4* gts     = (const float4*)d_in[3];     // (G,4)
    int A = in_sizes[0] / 2;
    int G = in_sizes[3] / 4;
    if (G > MAXG) G = MAXG;

    int grid1 = (A + K1_THREADS * K1_ITER - 1) / (K1_THREADS * K1_ITER);
    int nb = (A + CHUNK - 1) / CHUNK;   // 245 <= NB_MAX, all blocks co-resident

    k_iou<<<grid1, K1_THREADS>>>(anchors, gts, A, G);
    k_post<<<nb, 256>>>(score, regp, anchors, gts, (float*)d_out, out_size,
                        A, G, nb);
}